// round 16
// baseline (speedup 1.0000x reference)
#include <cuda_runtime.h>
#include <cuda_bf16.h>
#include <math_constants.h>

#define NPTS 16384
#define MCTR 4096
#define KNBR 32
#define FIN  64
#define RAD2 0.25f
#define MAXC 64

#define CLS  8       // FPS cluster size (CTAs)
#define TFPS 256     // threads per CTA (both roles)
#define PPT  8       // points per FPS thread
#define NPAIR (PPT / 2)
#define NW   (TFPS / 32)
#define NSLOT (CLS * NW)    // 64 warp-key slots per parity
#define NCONS 104           // consumer CTAs (13 clusters) — placement slack
#define GRID  (CLS + NCONS) // 112 = 14 clusters of 8

// consumer smem layout offsets (floats) after the 3*NPTS coordinate table
#define OFF_XB   (3 * NPTS)            // [32][68]
#define OFF_H1   (OFF_XB + 32 * 68)    // [32][64]
#define OFF_H2   (OFF_H1 + 32 * 64)    // [32][64]
#define OFF_OMAX (OFF_H2 + 32 * 64)    // [128] u32 max accum
#define OFF_CI   (OFF_OMAX + 128)      // [MAXC] int
#define OFF_CD   (OFF_CI + MAXC)       // [MAXC] float
#define OFF_SEL  (OFF_CD + MAXC)       // [KNBR] int
#define OFF_CNT  (OFF_SEL + KNBR)      // [1] int
#define OFF_FLG  (OFF_CNT + 1)         // [1] u32 broadcast of polled flag
#define SMEM_FLOATS (OFF_FLG + 1)

// ---------------- device scratch (no allocations allowed) ----------------
__device__ int      g_idx[MCTR];
__device__ unsigned g_flag[MCTR];   // (epoch<<14) | idx ; epoch guards replays
__device__ unsigned g_epoch;

__global__ void epoch_kernel() { if (threadIdx.x == 0) g_epoch = g_epoch + 1; }

__device__ __forceinline__ unsigned smem_u32(const void* p)
{
    unsigned a;
    asm("{ .reg .u64 t; cvta.to.shared.u64 t, %1; cvt.u32.u64 %0, t; }"
        : "=r"(a) : "l"(p));
    return a;
}
__device__ __forceinline__ unsigned ldg_vol_u32(const unsigned* p)
{
    unsigned v;
    asm volatile("ld.volatile.global.u32 %0, [%1];" : "=r"(v) : "l"(p) : "memory");
    return v;
}

#define PACK_F32X2(out, lo, hi) \
    asm("mov.b64 %0, {%1, %2};" : "=l"(out) : "f"(lo), "f"(hi))
#define UNPACK_F32X2(lo, hi, in) \
    asm("mov.b64 {%0, %1}, %2;" : "=f"(lo), "=f"(hi) : "l"(in))
#define ADD_X2(out, a, b) \
    asm("add.rn.f32x2 %0, %1, %2;" : "=l"(out) : "l"(a), "l"(b))
#define MUL_X2(out, a, b) \
    asm("mul.rn.f32x2 %0, %1, %2;" : "=l"(out) : "l"(a), "l"(b))

// ============ fused kernel: cluster 0 = FPS producer, rest = consumers ============
__global__ __launch_bounds__(TFPS, 1) __cluster_dims__(CLS, 1, 1)
void fused_kernel(const float* __restrict__ pos,
                  const float* __restrict__ feat,
                  const float* __restrict__ W1, const float* __restrict__ b1,
                  const float* __restrict__ W2, const float* __restrict__ b2,
                  const float* __restrict__ W3, const float* __restrict__ b3,
                  float* __restrict__ out, int out_size)
{
    extern __shared__ float dsm[];
    __shared__ unsigned long long s_mbox[2][NSLOT];

    const int t    = threadIdx.x;
    const int w    = t >> 5;
    const int lane = t & 31;
    const unsigned eh = g_epoch << 14;

    float* s_x = dsm;
    float* s_y = dsm + NPTS;
    float* s_z = dsm + 2 * NPTS;

    if (blockIdx.x < CLS) {
        // ================= FPS producer =================
        unsigned rank;
        asm("mov.u32 %0, %%cluster_ctarank;" : "=r"(rank));

        for (int i = t; i < NPTS; i += TFPS) {
            s_x[i] = pos[i * 3 + 0];
            s_y[i] = pos[i * 3 + 1];
            s_z[i] = pos[i * 3 + 2];
        }
        if (t < 2 * NSLOT) s_mbox[t >= NSLOT][t & (NSLOT - 1)] = 0ull;
        if (rank == 0 && t == 0) {
            g_idx[0] = 0;
            asm volatile("st.relaxed.gpu.global.u32 [%0], %1;"
                         :: "l"(&g_flag[0]), "r"(eh) : "memory");
        }
        __syncthreads();
        asm volatile("barrier.cluster.arrive.aligned;" ::: "memory");
        asm volatile("barrier.cluster.wait.aligned;"   ::: "memory");

        const unsigned a_slot_local = smem_u32(&s_mbox[0][rank * NW + w]);
        const unsigned a_poll       = smem_u32(&s_mbox[0][lane * 2]); // 2 contiguous slots
        unsigned a_remote = 0;
        if (lane < CLS) {
            asm("mapa.shared::cluster.u32 %0, %1, %2;"
                : "=r"(a_remote) : "r"(a_slot_local), "r"(lane));
        }

        const int base = (int)rank * (TFPS * PPT) + t;
        unsigned long long px2[NPAIR], py2[NPAIR], pz2[NPAIR];
        float dmin[PPT];
        #pragma unroll
        for (int j = 0; j < NPAIR; ++j) {
            int glo = base + (2 * j) * TFPS;
            int ghi = glo + TFPS;
            PACK_F32X2(px2[j], s_x[glo], s_x[ghi]);
            PACK_F32X2(py2[j], s_y[glo], s_y[ghi]);
            PACK_F32X2(pz2[j], s_z[glo], s_z[ghi]);
            dmin[2 * j] = CUDART_INF_F;
            dmin[2 * j + 1] = CUDART_INF_F;
        }
        float cx = s_x[0], cy = s_y[0], cz = s_z[0];

        for (int it = 1; it < MCTR; ++it) {
            const unsigned poff = (it & 1) ? (unsigned)(NSLOT * 8) : 0u;

            float ncx = -cx, ncy = -cy, ncz = -cz;
            unsigned long long ncx2, ncy2, ncz2;
            PACK_F32X2(ncx2, ncx, ncx);
            PACK_F32X2(ncy2, ncy, ncy);
            PACK_F32X2(ncz2, ncz, ncz);

            float bestv = -1.0f;
            int   bestk = 0;
            #pragma unroll
            for (int j = 0; j < NPAIR; ++j) {
                unsigned long long dx2, dy2, dz2, xx, yy, zz, s2, d2;
                ADD_X2(dx2, px2[j], ncx2);
                ADD_X2(dy2, py2[j], ncy2);
                ADD_X2(dz2, pz2[j], ncz2);
                MUL_X2(xx, dx2, dx2);
                MUL_X2(yy, dy2, dy2);
                MUL_X2(zz, dz2, dz2);
                ADD_X2(s2, xx, yy);
                ADD_X2(d2, s2, zz);
                float dlo, dhi;
                UNPACK_F32X2(dlo, dhi, d2);
                float m0 = fminf(dmin[2 * j], dlo);
                dmin[2 * j] = m0;
                if (m0 > bestv) { bestv = m0; bestk = 2 * j; }
                float m1 = fminf(dmin[2 * j + 1], dhi);
                dmin[2 * j + 1] = m1;
                if (m1 > bestv) { bestv = m1; bestk = 2 * j + 1; }
            }
            int besti = base + bestk * TFPS;

            unsigned vb   = __float_as_uint(bestv);
            unsigned wmax = __reduce_max_sync(0xffffffffu, vb);
            int cand = (vb == wmax) ? besti : 0x7fffffff;
            int wi   = __reduce_min_sync(0xffffffffu, cand);
            unsigned long long wkey =
                ((unsigned long long)wmax << 32)
              | ((unsigned long long)(0x3FFFu - (unsigned)wi) << 12)
              | (unsigned)it;

            if (lane < CLS) {
                asm volatile("st.relaxed.cluster.shared::cluster.b64 [%0], %1;"
                             :: "r"(a_remote + poff), "l"(wkey) : "memory");
            }

            // poll 2 contiguous local slots per lane via ONE vector LDS
            unsigned long long k0, k1;
            for (;;) {
                asm volatile("ld.volatile.shared.v2.u64 {%0, %1}, [%2];"
                             : "=l"(k0), "=l"(k1) : "r"(a_poll + poff) : "memory");
                bool ok = ((unsigned)(k0 & 0xFFFu) == (unsigned)it)
                       && ((unsigned)(k1 & 0xFFFu) == (unsigned)it);
                if (__all_sync(0xffffffffu, ok)) break;
            }
            unsigned long long k = (k0 > k1) ? k0 : k1;   // same tag -> pure key order
            unsigned hi   = (unsigned)(k >> 32);
            unsigned gmax = __reduce_max_sync(0xffffffffu, hi);
            unsigned lo   = (hi == gmax) ? (unsigned)k : 0u;
            unsigned glo  = __reduce_max_sync(0xffffffffu, lo);
            int gidx = (int)(0x3FFFu - ((glo >> 12) & 0x3FFFu));

            if (rank == 0 && w == 0 && lane == 0) {
                g_idx[it] = gidx;
                asm volatile("st.relaxed.gpu.global.u32 [%0], %1;"
                             :: "l"(&g_flag[it]), "r"(eh | (unsigned)gidx) : "memory");
            }

            cx = s_x[gidx]; cy = s_y[gidx]; cz = s_z[gidx];
        }

        asm volatile("barrier.cluster.arrive.aligned;" ::: "memory");
        asm volatile("barrier.cluster.wait.aligned;"   ::: "memory");
    } else {
        // ========== consumer: smem-cached ball query + MLP + tail per center ==========
        float*    xb    = dsm + OFF_XB;
        float*    h1    = dsm + OFF_H1;
        float*    h2    = dsm + OFF_H2;
        unsigned* omax  = (unsigned*)(dsm + OFF_OMAX);
        int*      s_ci  = (int*)(dsm + OFF_CI);
        float*    s_cd  = dsm + OFF_CD;
        int*      s_sel = (int*)(dsm + OFF_SEL);
        int*      s_cnt = (int*)(dsm + OFF_CNT);
        unsigned* s_flg = (unsigned*)(dsm + OFF_FLG);

        for (int i = t; i < NPTS; i += TFPS) {
            s_x[i] = pos[i * 3 + 0];
            s_y[i] = pos[i * 3 + 1];
            s_z[i] = pos[i * 3 + 2];
        }
        __syncthreads();

        const int cons = blockIdx.x - CLS;
        const bool has_tail  = (out_size >= MCTR * 128 + 3 * MCTR);
        const bool has_batch = (out_size >= MCTR * 128 + 3 * MCTR + MCTR);

        for (int m = cons; m < MCTR; m += NCONS) {
            // wait for FPS to publish center m — ONE thread polls (low power/traffic)
            if (t == 0) {
                unsigned f;
                int spins = 0;
                for (;;) {
                    f = ldg_vol_u32(&g_flag[m]);
                    if ((f & 0xFFFFC000u) == eh) break;
                    if (++spins > 16) __nanosleep(1000);   // deep backoff while idle
                }
                *s_flg = f;
            }
            if (t == 1) *s_cnt = 0;
            if (t < 128 + 2 && t >= 2) omax[t - 2] = 0u;   // relu outputs >= 0
            __syncthreads();
            const int cidx = (int)(*s_flg & 0x3FFFu);
            const float cx = s_x[cidx];
            const float cy = s_y[cidx];
            const float cz = s_z[cidx];

            // ball query from LOCAL smem (pure LDS)
            for (int i = t; i < NPTS; i += TFPS) {
                float dx = s_x[i] - cx, dy = s_y[i] - cy, dz = s_z[i] - cz;
                float d2 = __fadd_rn(__fadd_rn(__fmul_rn(dx, dx), __fmul_rn(dy, dy)),
                                     __fmul_rn(dz, dz));
                bool in = (d2 <= RAD2);
                unsigned mk = __ballot_sync(0xffffffffu, in);
                int bslot = 0;
                if (lane == 0) bslot = atomicAdd(s_cnt, __popc(mk));
                bslot = __shfl_sync(0xffffffffu, bslot, 0)
                      + __popc(mk & ((1u << lane) - 1u));
                if (in && bslot < MAXC) { s_ci[bslot] = i; s_cd[bslot] = d2; }
            }
            __syncthreads();
            int cnt = min(*s_cnt, MAXC);
            int nsel;
            if (cnt <= KNBR) {
                nsel = cnt;
                if (t < cnt) s_sel[t] = s_ci[t];
            } else {
                nsel = KNBR;
                // exact nearest-32 by (d2, idx) rank — set-identical to top_k+mask
                if (t < cnt) {
                    float d = s_cd[t];
                    int  ii = s_ci[t];
                    int r = 0;
                    for (int o = 0; o < cnt; ++o) {
                        float d2o = s_cd[o];
                        r += (d2o < d) || (d2o == d && s_ci[o] < ii);
                    }
                    if (r < KNBR) s_sel[r] = ii;
                }
            }
            __syncthreads();

            for (int k = w; k < nsel; k += 8) {
                int j = s_sel[k];
                xb[k * 68 + lane]      = feat[j * FIN + lane];
                xb[k * 68 + lane + 32] = feat[j * FIN + lane + 32];
                if (lane == 0) {
                    xb[k * 68 + 64] = s_x[j] - cx;
                    xb[k * 68 + 65] = s_y[j] - cy;
                    xb[k * 68 + 66] = s_z[j] - cz;
                }
            }
            __syncthreads();

            for (int p = t; p < nsel * 64; p += TFPS) {
                int k = p >> 6, o = p & 63;
                float acc = b1[o];
                #pragma unroll
                for (int i = 0; i < 67; ++i)
                    acc = fmaf(xb[k * 68 + i], W1[i * 64 + o], acc);
                h1[k * 64 + o] = fmaxf(acc, 0.0f);
            }
            __syncthreads();

            for (int p = t; p < nsel * 64; p += TFPS) {
                int k = p >> 6, o = p & 63;
                float acc = b2[o];
                #pragma unroll
                for (int i = 0; i < 64; ++i)
                    acc = fmaf(h1[k * 64 + i], W2[i * 64 + o], acc);
                h2[k * 64 + o] = fmaxf(acc, 0.0f);
            }
            __syncthreads();

            // layer 3 fused with max-aggregation (nonneg floats: u32-bit max exact)
            for (int p = t; p < nsel * 128; p += TFPS) {
                int k = p >> 7, o = p & 127;
                float acc = b3[o];
                #pragma unroll
                for (int i = 0; i < 64; ++i)
                    acc = fmaf(h2[k * 64 + i], W3[i * 128 + o], acc);
                float r3 = fmaxf(acc, 0.0f);
                atomicMax(&omax[o], __float_as_uint(r3));
            }
            __syncthreads();

            if (t < 128) out[m * 128 + t] = __uint_as_float(omax[t]);
            if (t == 128 && has_tail) {
                out[MCTR * 128 + 3 * m + 0] = s_x[cidx];
                out[MCTR * 128 + 3 * m + 1] = s_y[cidx];
                out[MCTR * 128 + 3 * m + 2] = s_z[cidx];
            }
            if (t == 129 && has_batch) {
                out[MCTR * 128 + 3 * MCTR + m] = 0.0f;
            }
            __syncthreads();   // protect smem reuse next center
        }
    }
}

extern "C" void kernel_launch(void* const* d_in, const int* in_sizes, int n_in,
                              void* d_out, int out_size)
{
    const float* feat = (const float*)d_in[0];
    const float* pos  = (const float*)d_in[1];
    const float* W1 = (const float*)d_in[3];
    const float* b1 = (const float*)d_in[4];
    const float* W2 = (const float*)d_in[5];
    const float* b2 = (const float*)d_in[6];
    const float* W3 = (const float*)d_in[7];
    const float* b3 = (const float*)d_in[8];
    float* out = (float*)d_out;

    const size_t fused_smem = SMEM_FLOATS * sizeof(float);   // ~217.6 KB
    cudaFuncSetAttribute(fused_kernel, cudaFuncAttributeMaxDynamicSharedMemorySize,
                         (int)fused_smem);

    epoch_kernel<<<1, 32>>>();
    fused_kernel<<<GRID, TFPS, fused_smem>>>(pos, feat, W1, b1, W2, b2, W3, b3,
                                             out, out_size);
}

// round 17
// speedup vs baseline: 1.2103x; 1.2103x over previous
#include <cuda_runtime.h>
#include <cuda_bf16.h>
#include <math_constants.h>

#define NPTS 16384
#define MCTR 4096
#define KNBR 32
#define FIN  64
#define RAD2 0.25f
#define MAXC 64

#define CLS  8       // FPS cluster size (CTAs)
#define TFPS 256     // threads per CTA (both roles)
#define PPT  8       // points per FPS thread
#define NPAIR (PPT / 2)
#define NW   (TFPS / 32)
#define NSLOT (CLS * NW)    // 64 warp-key slots per parity
#define NCONS 56            // consumer CTAs (7 clusters) — less DVFS/idle load
#define GRID  (CLS + NCONS) // 64 = 8 clusters of 8

// consumer smem layout offsets (floats) after the 3*NPTS coordinate table
#define OFF_XB   (3 * NPTS)            // [32][68]
#define OFF_H1   (OFF_XB + 32 * 68)    // [32][64]
#define OFF_H2   (OFF_H1 + 32 * 64)    // [32][64]
#define OFF_OMAX (OFF_H2 + 32 * 64)    // [128] u32 max accum
#define OFF_CI   (OFF_OMAX + 128)      // [MAXC] int
#define OFF_CD   (OFF_CI + MAXC)       // [MAXC] float
#define OFF_SEL  (OFF_CD + MAXC)       // [KNBR] int
#define OFF_CNT  (OFF_SEL + KNBR)      // [1] int
#define SMEM_FLOATS (OFF_CNT + 1)

// ---------------- device scratch (no allocations allowed) ----------------
// g_flag[m] = 0x80000000 | idx when ready; consumers clear to 0 after use.
// Zero-initialized at load; consume-and-clear keeps graph replays deterministic.
__device__ unsigned g_flag[MCTR];

__device__ __forceinline__ unsigned smem_u32(const void* p)
{
    unsigned a;
    asm("{ .reg .u64 t; cvta.to.shared.u64 t, %1; cvt.u32.u64 %0, t; }"
        : "=r"(a) : "l"(p));
    return a;
}
__device__ __forceinline__ unsigned long long lds_vol_u64(unsigned a)
{
    unsigned long long v;
    asm volatile("ld.volatile.shared.b64 %0, [%1];" : "=l"(v) : "r"(a) : "memory");
    return v;
}
__device__ __forceinline__ unsigned ldg_vol_u32(const unsigned* p)
{
    unsigned v;
    asm volatile("ld.volatile.global.u32 %0, [%1];" : "=r"(v) : "l"(p) : "memory");
    return v;
}
__device__ __forceinline__ void stg_rel_u32(unsigned* p, unsigned v)
{
    asm volatile("st.relaxed.gpu.global.u32 [%0], %1;" :: "l"(p), "r"(v) : "memory");
}

#define PACK_F32X2(out, lo, hi) \
    asm("mov.b64 %0, {%1, %2};" : "=l"(out) : "f"(lo), "f"(hi))
#define UNPACK_F32X2(lo, hi, in) \
    asm("mov.b64 {%0, %1}, %2;" : "=f"(lo), "=f"(hi) : "l"(in))
#define ADD_X2(out, a, b) \
    asm("add.rn.f32x2 %0, %1, %2;" : "=l"(out) : "l"(a), "l"(b))
#define MUL_X2(out, a, b) \
    asm("mul.rn.f32x2 %0, %1, %2;" : "=l"(out) : "l"(a), "l"(b))

// ============ fused kernel: cluster 0 = FPS producer, rest = consumers ============
__global__ __launch_bounds__(TFPS, 1) __cluster_dims__(CLS, 1, 1)
void fused_kernel(const float* __restrict__ pos,
                  const float* __restrict__ feat,
                  const float* __restrict__ W1, const float* __restrict__ b1,
                  const float* __restrict__ W2, const float* __restrict__ b2,
                  const float* __restrict__ W3, const float* __restrict__ b3,
                  float* __restrict__ out, int out_size)
{
    extern __shared__ float dsm[];
    __shared__ unsigned long long s_mbox[2][NSLOT];

    const int t    = threadIdx.x;
    const int w    = t >> 5;
    const int lane = t & 31;

    float* s_x = dsm;
    float* s_y = dsm + NPTS;
    float* s_z = dsm + 2 * NPTS;

    if (blockIdx.x < CLS) {
        // ================= FPS producer (R12/R15 chain, unchanged) =================
        unsigned rank;
        asm("mov.u32 %0, %%cluster_ctarank;" : "=r"(rank));

        for (int i = t; i < NPTS; i += TFPS) {
            s_x[i] = pos[i * 3 + 0];
            s_y[i] = pos[i * 3 + 1];
            s_z[i] = pos[i * 3 + 2];
        }
        if (t < 2 * NSLOT) s_mbox[t >= NSLOT][t & (NSLOT - 1)] = 0ull;
        if (rank == 0 && t == 0) {
            stg_rel_u32(&g_flag[0], 0x80000000u);   // center 0 = point 0
        }
        __syncthreads();
        asm volatile("barrier.cluster.arrive.aligned;" ::: "memory");
        asm volatile("barrier.cluster.wait.aligned;"   ::: "memory");

        const unsigned a_slot_local = smem_u32(&s_mbox[0][rank * NW + w]);
        const unsigned a_poll0      = smem_u32(&s_mbox[0][lane]);
        const unsigned a_poll1      = smem_u32(&s_mbox[0][lane + 32]);
        unsigned a_remote = 0;
        if (lane < CLS) {
            asm("mapa.shared::cluster.u32 %0, %1, %2;"
                : "=r"(a_remote) : "r"(a_slot_local), "r"(lane));
        }

        const int base = (int)rank * (TFPS * PPT) + t;
        unsigned long long px2[NPAIR], py2[NPAIR], pz2[NPAIR];
        float dmin[PPT];
        #pragma unroll
        for (int j = 0; j < NPAIR; ++j) {
            int glo = base + (2 * j) * TFPS;
            int ghi = glo + TFPS;
            PACK_F32X2(px2[j], s_x[glo], s_x[ghi]);
            PACK_F32X2(py2[j], s_y[glo], s_y[ghi]);
            PACK_F32X2(pz2[j], s_z[glo], s_z[ghi]);
            dmin[2 * j] = CUDART_INF_F;
            dmin[2 * j + 1] = CUDART_INF_F;
        }
        float cx = s_x[0], cy = s_y[0], cz = s_z[0];

        for (int it = 1; it < MCTR; ++it) {
            const unsigned poff = (it & 1) ? (unsigned)(NSLOT * 8) : 0u;

            float ncx = -cx, ncy = -cy, ncz = -cz;
            unsigned long long ncx2, ncy2, ncz2;
            PACK_F32X2(ncx2, ncx, ncx);
            PACK_F32X2(ncy2, ncy, ncy);
            PACK_F32X2(ncz2, ncz, ncz);

            float bestv = -1.0f;
            int   bestk = 0;
            #pragma unroll
            for (int j = 0; j < NPAIR; ++j) {
                unsigned long long dx2, dy2, dz2, xx, yy, zz, s2, d2;
                ADD_X2(dx2, px2[j], ncx2);
                ADD_X2(dy2, py2[j], ncy2);
                ADD_X2(dz2, pz2[j], ncz2);
                MUL_X2(xx, dx2, dx2);
                MUL_X2(yy, dy2, dy2);
                MUL_X2(zz, dz2, dz2);
                ADD_X2(s2, xx, yy);
                ADD_X2(d2, s2, zz);
                float dlo, dhi;
                UNPACK_F32X2(dlo, dhi, d2);
                float m0 = fminf(dmin[2 * j], dlo);
                dmin[2 * j] = m0;
                if (m0 > bestv) { bestv = m0; bestk = 2 * j; }
                float m1 = fminf(dmin[2 * j + 1], dhi);
                dmin[2 * j + 1] = m1;
                if (m1 > bestv) { bestv = m1; bestk = 2 * j + 1; }
            }
            int besti = base + bestk * TFPS;

            unsigned vb   = __float_as_uint(bestv);
            unsigned wmax = __reduce_max_sync(0xffffffffu, vb);
            int cand = (vb == wmax) ? besti : 0x7fffffff;
            int wi   = __reduce_min_sync(0xffffffffu, cand);
            unsigned long long wkey =
                ((unsigned long long)wmax << 32)
              | ((unsigned long long)(0x3FFFu - (unsigned)wi) << 12)
              | (unsigned)it;

            if (lane < CLS) {
                asm volatile("st.relaxed.cluster.shared::cluster.b64 [%0], %1;"
                             :: "r"(a_remote + poff), "l"(wkey) : "memory");
            }

            unsigned long long k0, k1;
            for (;;) {
                k0 = lds_vol_u64(a_poll0 + poff);
                k1 = lds_vol_u64(a_poll1 + poff);
                bool ok = ((unsigned)(k0 & 0xFFFu) == (unsigned)it)
                       && ((unsigned)(k1 & 0xFFFu) == (unsigned)it);
                if (__all_sync(0xffffffffu, ok)) break;
            }
            unsigned long long k = (k0 > k1) ? k0 : k1;
            unsigned hi   = (unsigned)(k >> 32);
            unsigned gmax = __reduce_max_sync(0xffffffffu, hi);
            unsigned lo   = (hi == gmax) ? (unsigned)k : 0u;
            unsigned glo  = __reduce_max_sync(0xffffffffu, lo);
            int gidx = (int)(0x3FFFu - ((glo >> 12) & 0x3FFFu));

            if (rank == 0 && w == 0 && lane == 0) {
                stg_rel_u32(&g_flag[it], 0x80000000u | (unsigned)gidx);
            }

            cx = s_x[gidx]; cy = s_y[gidx]; cz = s_z[gidx];
        }

        asm volatile("barrier.cluster.arrive.aligned;" ::: "memory");
        asm volatile("barrier.cluster.wait.aligned;"   ::: "memory");
    } else {
        // ========== consumer: smem-cached ball query + MLP + tail per center ==========
        float*    xb    = dsm + OFF_XB;
        float*    h1    = dsm + OFF_H1;
        float*    h2    = dsm + OFF_H2;
        unsigned* omax  = (unsigned*)(dsm + OFF_OMAX);
        int*      s_ci  = (int*)(dsm + OFF_CI);
        float*    s_cd  = dsm + OFF_CD;
        int*      s_sel = (int*)(dsm + OFF_SEL);
        int*      s_cnt = (int*)(dsm + OFF_CNT);

        for (int i = t; i < NPTS; i += TFPS) {
            s_x[i] = pos[i * 3 + 0];
            s_y[i] = pos[i * 3 + 1];
            s_z[i] = pos[i * 3 + 2];
        }
        __syncthreads();

        const int cons = blockIdx.x - CLS;
        const bool has_tail  = (out_size >= MCTR * 128 + 3 * MCTR);
        const bool has_batch = (out_size >= MCTR * 128 + 3 * MCTR + MCTR);

        for (int m = cons; m < MCTR; m += NCONS) {
            // wait for FPS to publish center m (bit31-valid; cleared after use)
            unsigned f;
            int spins = 0;
            for (;;) {
                f = ldg_vol_u32(&g_flag[m]);
                if (f & 0x80000000u) break;
                if (++spins > 64) __nanosleep(200);
            }
            const int cidx = (int)(f & 0x3FFFu);
            const float cx = s_x[cidx];
            const float cy = s_y[cidx];
            const float cz = s_z[cidx];

            if (t == 0) *s_cnt = 0;
            if (t < 128) omax[t] = 0u;   // relu outputs are >= 0
            __syncthreads();

            // ball query from LOCAL smem (pure LDS)
            for (int i = t; i < NPTS; i += TFPS) {
                float dx = s_x[i] - cx, dy = s_y[i] - cy, dz = s_z[i] - cz;
                float d2 = __fadd_rn(__fadd_rn(__fmul_rn(dx, dx), __fmul_rn(dy, dy)),
                                     __fmul_rn(dz, dz));
                bool in = (d2 <= RAD2);
                unsigned mk = __ballot_sync(0xffffffffu, in);
                int bslot = 0;
                if (lane == 0) bslot = atomicAdd(s_cnt, __popc(mk));
                bslot = __shfl_sync(0xffffffffu, bslot, 0)
                      + __popc(mk & ((1u << lane) - 1u));
                if (in && bslot < MAXC) { s_ci[bslot] = i; s_cd[bslot] = d2; }
            }
            __syncthreads();
            int cnt = min(*s_cnt, MAXC);
            int nsel;
            if (cnt <= KNBR) {
                nsel = cnt;
                if (t < cnt) s_sel[t] = s_ci[t];
            } else {
                nsel = KNBR;
                // exact nearest-32 by (d2, idx) rank — set-identical to top_k+mask
                if (t < cnt) {
                    float d = s_cd[t];
                    int  ii = s_ci[t];
                    int r = 0;
                    for (int o = 0; o < cnt; ++o) {
                        float d2o = s_cd[o];
                        r += (d2o < d) || (d2o == d && s_ci[o] < ii);
                    }
                    if (r < KNBR) s_sel[r] = ii;
                }
            }
            __syncthreads();

            for (int k = w; k < nsel; k += 8) {
                int j = s_sel[k];
                xb[k * 68 + lane]      = feat[j * FIN + lane];
                xb[k * 68 + lane + 32] = feat[j * FIN + lane + 32];
                if (lane == 0) {
                    xb[k * 68 + 64] = s_x[j] - cx;
                    xb[k * 68 + 65] = s_y[j] - cy;
                    xb[k * 68 + 66] = s_z[j] - cz;
                }
            }
            __syncthreads();

            for (int p = t; p < nsel * 64; p += TFPS) {
                int k = p >> 6, o = p & 63;
                float acc = b1[o];
                #pragma unroll
                for (int i = 0; i < 67; ++i)
                    acc = fmaf(xb[k * 68 + i], W1[i * 64 + o], acc);
                h1[k * 64 + o] = fmaxf(acc, 0.0f);
            }
            __syncthreads();

            for (int p = t; p < nsel * 64; p += TFPS) {
                int k = p >> 6, o = p & 63;
                float acc = b2[o];
                #pragma unroll
                for (int i = 0; i < 64; ++i)
                    acc = fmaf(h1[k * 64 + i], W2[i * 64 + o], acc);
                h2[k * 64 + o] = fmaxf(acc, 0.0f);
            }
            __syncthreads();

            // layer 3 fused with max-aggregation (nonneg floats: u32-bit max exact)
            for (int p = t; p < nsel * 128; p += TFPS) {
                int k = p >> 7, o = p & 127;
                float acc = b3[o];
                #pragma unroll
                for (int i = 0; i < 64; ++i)
                    acc = fmaf(h2[k * 64 + i], W3[i * 128 + o], acc);
                float r3 = fmaxf(acc, 0.0f);
                atomicMax(&omax[o], __float_as_uint(r3));
            }
            __syncthreads();

            if (t < 128) out[m * 128 + t] = __uint_as_float(omax[t]);
            if (t == 128 && has_tail) {
                out[MCTR * 128 + 3 * m + 0] = s_x[cidx];
                out[MCTR * 128 + 3 * m + 1] = s_y[cidx];
                out[MCTR * 128 + 3 * m + 2] = s_z[cidx];
            }
            if (t == 129 && has_batch) {
                out[MCTR * 128 + 3 * MCTR + m] = 0.0f;
            }
            __syncthreads();            // all reads of flag/smem done
            if (t == 0) stg_rel_u32(&g_flag[m], 0u);   // consume-and-clear (replay-safe)
        }
    }
}

extern "C" void kernel_launch(void* const* d_in, const int* in_sizes, int n_in,
                              void* d_out, int out_size)
{
    const float* feat = (const float*)d_in[0];
    const float* pos  = (const float*)d_in[1];
    const float* W1 = (const float*)d_in[3];
    const float* b1 = (const float*)d_in[4];
    const float* W2 = (const float*)d_in[5];
    const float* b2 = (const float*)d_in[6];
    const float* W3 = (const float*)d_in[7];
    const float* b3 = (const float*)d_in[8];
    float* out = (float*)d_out;

    const size_t fused_smem = SMEM_FLOATS * sizeof(float);   // ~217.6 KB
    cudaFuncSetAttribute(fused_kernel, cudaFuncAttributeMaxDynamicSharedMemorySize,
                         (int)fused_smem);

    fused_kernel<<<GRID, TFPS, fused_smem>>>(pos, feat, W1, b1, W2, b2, W3, b3,
                                             out, out_size);
}